// round 2
// baseline (speedup 1.0000x reference)
#include <cuda_runtime.h>

#define H_ 512
#define W_ 512
#define C_ 32
#define B_ 2
#define N_ 120000
#define HW_ (H_*W_)

typedef unsigned long long u64;

// ---- device scratch (no allocations allowed) ----
__device__ __align__(128) float g_Q[B_*N_*C_];
__device__ __align__(128) float g_K[B_*N_*C_];
__device__ __align__(128) float g_V[B_*N_*C_];
__device__ __align__(128) float g_O[B_*N_*C_];
__device__ int   g_grid[B_*HW_];
__device__ float g_A[3*1024];     // fused A_q(,*0.25), A_k, A_v  (row-major [c][e])
__device__ float g_bf[3*32];      // fused biases (q scaled by 0.25)
__device__ float g_posP[9*32];    // pos embedding projected through in_w[2C:]

// ---- packed f32x2 helpers (FFMA2 only reachable via PTX) ----
__device__ __forceinline__ u64 pk2(float lo, float hi){
    u64 r; asm("mov.b64 %0, {%1, %2};" : "=l"(r) : "f"(lo), "f"(hi)); return r;
}
__device__ __forceinline__ float2 unpk2(u64 v){
    float2 f; asm("mov.b64 {%0, %1}, %2;" : "=f"(f.x), "=f"(f.y) : "l"(v)); return f;
}
__device__ __forceinline__ u64 ffma2(u64 a, u64 b, u64 c){
    u64 d; asm("fma.rn.f32x2 %0, %1, %2, %3;" : "=l"(d) : "l"(a), "l"(b), "l"(c)); return d;
}
__device__ __forceinline__ float hsum2(u64 a){ float2 f = unpk2(a); return f.x + f.y; }

// ---------------------------------------------------------------
// K0: fold (wq,bq,in_w[:C],in_b[:C]) -> A_q,b_q (scaled 0.25), etc. + posP
// ---------------------------------------------------------------
__global__ void k_setup(const float* __restrict__ wq, const float* __restrict__ bq,
                        const float* __restrict__ wk, const float* __restrict__ bk,
                        const float* __restrict__ wv, const float* __restrict__ bv,
                        const float* __restrict__ in_w, const float* __restrict__ in_b,
                        const float* __restrict__ pos_w, const float* __restrict__ pos_b){
    int t = threadIdx.x;
    if (t >= 96) return;
    int m = t >> 5, c = t & 31;
    const float* Wm = (m==0) ? wq : (m==1) ? wk : wv;
    const float* bm = (m==0) ? bq : (m==1) ? bk : bv;
    const float* iw = in_w + (m*32 + c)*32;
    float scale = (m==0) ? 0.25f : 1.0f;   // 1/sqrt(HD=16)
    for (int e = 0; e < 32; e++){
        float a = 0.f;
        for (int d = 0; d < 32; d++) a += iw[d] * Wm[d*32 + e];
        g_A[m*1024 + c*32 + e] = a * scale;
    }
    float bb = 0.f;
    for (int d = 0; d < 32; d++) bb += iw[d] * bm[d];
    g_bf[m*32 + c] = (bb + in_b[m*32 + c]) * scale;
    if (m == 2){
        const int dr[9] = {0,-1,1,0,-1,1,0,-1,1};
        const int dc[9] = {0,0,0,1,1,1,-1,-1,-1};
        for (int s = 0; s < 9; s++){
            float a = 0.f;
            for (int d = 0; d < 32; d++){
                float pos = (float)dr[s]*pos_w[d*2+0] + (float)dc[s]*pos_w[d*2+1] + pos_b[d];
                a += iw[d] * pos;
            }
            g_posP[s*32 + c] = a;
        }
    }
}

// ---------------------------------------------------------------
// K1: dense grid build
// ---------------------------------------------------------------
__global__ void k_grid_clear(){
    int i = blockIdx.x*blockDim.x + threadIdx.x;
    if (i < B_*HW_) g_grid[i] = -1;
}
__global__ void k_grid_fill(const int* __restrict__ coors){
    int p = blockIdx.x*blockDim.x + threadIdx.x;
    if (p >= B_*N_) return;
    int b = p / N_, n = p % N_;
    int r = coors[2*p], c = coors[2*p+1];
    g_grid[b*HW_ + r*W_ + c] = n;
}

// ---------------------------------------------------------------
// K2: per-point LayerNorm + 3 fused 32x32 matvecs -> Q,K,V rows
// ---------------------------------------------------------------
__global__ void __launch_bounds__(256) k_qkv(const float* __restrict__ feats,
                                             const float* __restrict__ ln_w,
                                             const float* __restrict__ ln_b){
    __shared__ __align__(16) float shA[3*1024];
    __shared__ float shB[96];
    __shared__ float shLW[32], shLB[32];
    int t = threadIdx.x;
    for (int i = t; i < 3072; i += 256) shA[i] = g_A[i];
    if (t < 96) shB[t] = g_bf[t];
    if (t < 32){ shLW[t] = ln_w[t]; shLB[t] = ln_b[t]; }
    __syncthreads();
    int p = blockIdx.x*256 + t;
    if (p >= B_*N_) return;

    const float4* xin = (const float4*)(feats + (size_t)p*C_);
    float x[32];
#pragma unroll
    for (int k = 0; k < 8; k++){
        float4 v = xin[k];
        x[4*k] = v.x; x[4*k+1] = v.y; x[4*k+2] = v.z; x[4*k+3] = v.w;
    }
    float mu = 0.f;
#pragma unroll
    for (int e = 0; e < 32; e++) mu += x[e];
    mu *= (1.f/32.f);
    float var = 0.f;
#pragma unroll
    for (int e = 0; e < 32; e++){ float d = x[e]-mu; var += d*d; }
    var *= (1.f/32.f);
    float inv = rsqrtf(var + 1e-5f);
    u64 xp[16];
#pragma unroll
    for (int k = 0; k < 16; k++){
        float a  = (x[2*k  ]-mu)*inv*shLW[2*k  ] + shLB[2*k  ];
        float b2 = (x[2*k+1]-mu)*inv*shLW[2*k+1] + shLB[2*k+1];
        xp[k] = pk2(a, b2);
    }
#pragma unroll
    for (int m = 0; m < 3; m++){
        float4* dst4 = (float4*)((m==0 ? g_Q : (m==1 ? g_K : g_V)) + (size_t)p*C_);
#pragma unroll 2
        for (int c4 = 0; c4 < 8; c4++){
            float r[4];
#pragma unroll
            for (int j = 0; j < 4; j++){
                int c = c4*4 + j;
                u64 acc = pk2(shB[m*32+c], 0.f);
                const u64* Ar = (const u64*)&shA[m*1024 + c*32];
#pragma unroll
                for (int k = 0; k < 16; k++) acc = ffma2(Ar[k], xp[k], acc);
                r[j] = hsum2(acc);
            }
            dst4[c4] = make_float4(r[0], r[1], r[2], r[3]);
        }
    }
}

// ---------------------------------------------------------------
// K3: per-point 9-neighbor 2-head attention + output projection
// ---------------------------------------------------------------
__global__ void __launch_bounds__(256) k_attn(const int* __restrict__ coors,
                                              const float* __restrict__ in_b,
                                              const float* __restrict__ out_w,
                                              const float* __restrict__ out_b){
    __shared__ __align__(16) float shW[1024];
    __shared__ __align__(16) float shPos[9*32];
    __shared__ __align__(16) float shKinv[32];
    __shared__ __align__(16) float shVinv[32];
    __shared__ float shOB[32];
    int t = threadIdx.x;
    for (int i = t; i < 1024; i += 256) shW[i] = out_w[i];
    for (int i = t; i < 288; i += 256) shPos[i] = g_posP[i];
    if (t < 32){ shKinv[t] = in_b[32+t]; shVinv[t] = in_b[64+t]; shOB[t] = out_b[t]; }
    __syncthreads();
    int p = blockIdx.x*256 + t;
    if (p >= B_*N_) return;
    int b = p / N_;

    const float4* qin = (const float4*)(g_Q + (size_t)p*C_);
    u64 qp[16];
#pragma unroll
    for (int k = 0; k < 8; k++){
        float4 v = qin[k];
        qp[2*k] = pk2(v.x, v.y); qp[2*k+1] = pk2(v.z, v.w);
    }
    int r0 = coors[2*p], c0 = coors[2*p+1];
    const int* grid = g_grid + b*HW_;
    const int dr[9] = {0,-1,1,0,-1,1,0,-1,1};
    const int dc[9] = {0,0,0,1,1,1,-1,-1,-1};
    int idx[9];
#pragma unroll
    for (int s = 0; s < 9; s++){
        int rr = r0 + dr[s], cc = c0 + dc[s];
        bool ok = (rr >= 0) && (rr < H_) && (cc >= 0) && (cc < W_);
        idx[s] = ok ? grid[rr*W_ + cc] : -1;
    }
    // logit of an invalid slot: q . in_b[C:2C]  (q already carries the 0.25 scale)
    const u64* kinvp = (const u64*)shKinv;
    u64 ai0 = 0ull, ai1 = 0ull;
#pragma unroll
    for (int k = 0; k < 8; k++){
        ai0 = ffma2(qp[k],   kinvp[k],   ai0);
        ai1 = ffma2(qp[8+k], kinvp[8+k], ai1);
    }
    float linv0 = hsum2(ai0), linv1 = hsum2(ai1);

    float lg[18];
#pragma unroll
    for (int s = 0; s < 9; s++){
        if (idx[s] >= 0){
            const float4* kr = (const float4*)(g_K + (size_t)(b*N_ + idx[s])*C_);
            u64 a0 = 0ull, a1 = 0ull;
#pragma unroll
            for (int k = 0; k < 4; k++){
                float4 v = kr[k];
                a0 = ffma2(qp[2*k],   pk2(v.x, v.y), a0);
                a0 = ffma2(qp[2*k+1], pk2(v.z, v.w), a0);
            }
#pragma unroll
            for (int k = 4; k < 8; k++){
                float4 v = kr[k];
                a1 = ffma2(qp[2*k],   pk2(v.x, v.y), a1);
                a1 = ffma2(qp[2*k+1], pk2(v.z, v.w), a1);
            }
            lg[s] = hsum2(a0); lg[9+s] = hsum2(a1);
        } else {
            lg[s] = linv0; lg[9+s] = linv1;
        }
    }
    float m0 = lg[0], m1 = lg[9];
#pragma unroll
    for (int s = 1; s < 9; s++){ m0 = fmaxf(m0, lg[s]); m1 = fmaxf(m1, lg[9+s]); }
    float sum0 = 0.f, sum1 = 0.f;
#pragma unroll
    for (int s = 0; s < 9; s++){
        lg[s]   = __expf(lg[s]   - m0); sum0 += lg[s];
        lg[9+s] = __expf(lg[9+s] - m1); sum1 += lg[9+s];
    }
    float rs0 = 1.f/sum0, rs1 = 1.f/sum1;

    u64 ov[16];
#pragma unroll
    for (int k = 0; k < 16; k++) ov[k] = 0ull;
    float w0inv = 0.f, w1inv = 0.f;
#pragma unroll
    for (int s = 0; s < 9; s++){
        float ws0 = lg[s]*rs0, ws1 = lg[9+s]*rs1;
        if (idx[s] >= 0){
            const float4* vr = (const float4*)(g_V + (size_t)(b*N_ + idx[s])*C_);
            const float4* pr = (const float4*)&shPos[s*32];
            u64 W0 = pk2(ws0, ws0), W1 = pk2(ws1, ws1);
#pragma unroll
            for (int k = 0; k < 4; k++){
                float4 v = vr[k]; float4 pp = pr[k];
                ov[2*k]   = ffma2(W0, pk2(v.x+pp.x, v.y+pp.y), ov[2*k]);
                ov[2*k+1] = ffma2(W0, pk2(v.z+pp.z, v.w+pp.w), ov[2*k+1]);
            }
#pragma unroll
            for (int k = 4; k < 8; k++){
                float4 v = vr[k]; float4 pp = pr[k];
                ov[2*k]   = ffma2(W1, pk2(v.x+pp.x, v.y+pp.y), ov[2*k]);
                ov[2*k+1] = ffma2(W1, pk2(v.z+pp.z, v.w+pp.w), ov[2*k+1]);
            }
        } else { w0inv += ws0; w1inv += ws1; }
    }
    {   // invalid slots contribute weight * in_b[2C:3C]
        const u64* vinvp = (const u64*)shVinv;
        u64 W0 = pk2(w0inv, w0inv), W1 = pk2(w1inv, w1inv);
#pragma unroll
        for (int k = 0; k < 8; k++){
            ov[k]   = ffma2(W0, vinvp[k],   ov[k]);
            ov[8+k] = ffma2(W1, vinvp[8+k], ov[8+k]);
        }
    }
    // output projection: o2 = out_b + out_w @ o
    float4* orow = (float4*)(g_O + (size_t)p*C_);
#pragma unroll 2
    for (int c4 = 0; c4 < 8; c4++){
        float r[4];
#pragma unroll
        for (int j = 0; j < 4; j++){
            int c = c4*4 + j;
            u64 acc = pk2(shOB[c], 0.f);
            const u64* Wr = (const u64*)&shW[c*32];
#pragma unroll
            for (int k = 0; k < 16; k++) acc = ffma2(Wr[k], ov[k], acc);
            r[j] = hsum2(acc);
        }
        orow[c4] = make_float4(r[0], r[1], r[2], r[3]);
    }
}

// ---------------------------------------------------------------
// K4: expand to [B,C,H,W] — full-row gathers + smem transpose,
//     coalesced channel-major stores (avoids 8x write amplification)
// ---------------------------------------------------------------
__global__ void __launch_bounds__(256) k_expand(float* __restrict__ out){
    __shared__ float sm[256*33];
    int b   = blockIdx.y;
    int hw0 = blockIdx.x * 256;
    int t   = threadIdx.x;
    int hw  = hw0 + t;
    int idx = g_grid[b*HW_ + hw];
    if (idx >= 0){
        const float4* orow = (const float4*)(g_O + (size_t)(b*N_ + idx)*C_);
#pragma unroll
        for (int k = 0; k < 8; k++){
            float4 v = orow[k];
            sm[t*33 + 4*k + 0] = v.x; sm[t*33 + 4*k + 1] = v.y;
            sm[t*33 + 4*k + 2] = v.z; sm[t*33 + 4*k + 3] = v.w;
        }
    } else {
#pragma unroll
        for (int c = 0; c < 32; c++) sm[t*33 + c] = 0.f;
    }
    __syncthreads();
#pragma unroll
    for (int c = 0; c < 32; c++)
        out[((size_t)(b*C_ + c))*HW_ + hw] = sm[t*33 + c];
}

// ---------------------------------------------------------------
extern "C" void kernel_launch(void* const* d_in, const int* in_sizes, int n_in,
                              void* d_out, int out_size){
    const float* feats = (const float*)d_in[0];
    const int*   coors = (const int*)  d_in[1];
    const float* ln_w  = (const float*)d_in[2];
    const float* ln_b  = (const float*)d_in[3];
    const float* wq    = (const float*)d_in[4];
    const float* bq    = (const float*)d_in[5];
    const float* wk    = (const float*)d_in[6];
    const float* bk    = (const float*)d_in[7];
    const float* wv    = (const float*)d_in[8];
    const float* bv    = (const float*)d_in[9];
    const float* pos_w = (const float*)d_in[10];
    const float* pos_b = (const float*)d_in[11];
    const float* in_w  = (const float*)d_in[12];
    const float* in_b  = (const float*)d_in[13];
    const float* out_w = (const float*)d_in[14];
    const float* out_b = (const float*)d_in[15];

    k_setup<<<1, 96>>>(wq, bq, wk, bk, wv, bv, in_w, in_b, pos_w, pos_b);
    k_grid_clear<<<(B_*HW_ + 255)/256, 256>>>();
    k_grid_fill<<<(B_*N_ + 255)/256, 256>>>(coors);
    k_qkv<<<(B_*N_ + 255)/256, 256>>>(feats, ln_w, ln_b);
    k_attn<<<(B_*N_ + 255)/256, 256>>>(coors, in_b, out_w, out_b);
    k_expand<<<dim3(HW_/256, B_), 256>>>((float*)d_out);
}

// round 5
// speedup vs baseline: 1.0100x; 1.0100x over previous
#include <cuda_runtime.h>

#define H_ 512
#define W_ 512
#define C_ 32
#define B_ 2
#define N_ 120000
#define HW_ (H_*W_)
#define NP_ (B_*N_)

typedef unsigned long long u64;

// ---- device scratch (no allocations allowed) ----
__device__ __align__(128) float g_Q[NP_*C_];
__device__ __align__(128) float g_K[NP_*C_];
__device__ __align__(128) float g_V[NP_*C_];
__device__ __align__(128) float g_O[NP_*C_];
__device__ int   g_grid[B_*HW_];
__device__ float g_A[3*1024];     // fused A_q(*0.25), A_k, A_v  (row-major [ch][e], ch=m*32+c)
__device__ float g_bf[3*32];      // fused biases (q scaled by 0.25)
__device__ float g_posP[9*32];    // pos embedding projected through in_w[2C:]

// ---- packed f32x2 helpers ----
__device__ __forceinline__ u64 pk2(float lo, float hi){
    u64 r; asm("mov.b64 %0, {%1, %2};" : "=l"(r) : "f"(lo), "f"(hi)); return r;
}
__device__ __forceinline__ float2 unpk2(u64 v){
    float2 f; asm("mov.b64 {%0, %1}, %2;" : "=f"(f.x), "=f"(f.y) : "l"(v)); return f;
}
__device__ __forceinline__ u64 ffma2(u64 a, u64 b, u64 c){
    u64 d; asm("fma.rn.f32x2 %0, %1, %2, %3;" : "=l"(d) : "l"(a), "l"(b), "l"(c)); return d;
}
__device__ __forceinline__ float hsum2(u64 a){ float2 f = unpk2(a); return f.x + f.y; }

// ---------------------------------------------------------------
// K0: fold (wq,bq,in_w[:C],in_b[:C]) -> A_q,b_q (scaled 0.25), etc. + posP
// ---------------------------------------------------------------
__global__ void k_setup(const float* __restrict__ wq, const float* __restrict__ bq,
                        const float* __restrict__ wk, const float* __restrict__ bk,
                        const float* __restrict__ wv, const float* __restrict__ bv,
                        const float* __restrict__ in_w, const float* __restrict__ in_b,
                        const float* __restrict__ pos_w, const float* __restrict__ pos_b){
    int t = threadIdx.x;
    if (t >= 96) return;
    int m = t >> 5, c = t & 31;
    const float* Wm = (m==0) ? wq : (m==1) ? wk : wv;
    const float* bm = (m==0) ? bq : (m==1) ? bk : bv;
    const float* iw = in_w + (m*32 + c)*32;
    float scale = (m==0) ? 0.25f : 1.0f;   // 1/sqrt(HD=16)
    for (int e = 0; e < 32; e++){
        float a = 0.f;
        for (int d = 0; d < 32; d++) a += iw[d] * Wm[d*32 + e];
        g_A[m*1024 + c*32 + e] = a * scale;
    }
    float bb = 0.f;
    for (int d = 0; d < 32; d++) bb += iw[d] * bm[d];
    g_bf[m*32 + c] = (bb + in_b[m*32 + c]) * scale;
    if (m == 2){
        const int dr[9] = {0,-1,1,0,-1,1,0,-1,1};
        const int dc[9] = {0,0,0,1,1,1,-1,-1,-1};
        for (int s = 0; s < 9; s++){
            float a = 0.f;
            for (int d = 0; d < 32; d++){
                float pos = (float)dr[s]*pos_w[d*2+0] + (float)dc[s]*pos_w[d*2+1] + pos_b[d];
                a += iw[d] * pos;
            }
            g_posP[s*32 + c] = a;
        }
    }
}

// ---------------------------------------------------------------
// K1: dense grid build
// ---------------------------------------------------------------
__global__ void k_grid_clear(){
    int i = blockIdx.x*blockDim.x + threadIdx.x;
    if (i < B_*HW_) g_grid[i] = -1;
}
__global__ void k_grid_fill(const int* __restrict__ coors){
    int p = blockIdx.x*blockDim.x + threadIdx.x;
    if (p >= NP_) return;
    int b = p / N_, n = p % N_;
    int r = coors[2*p], c = coors[2*p+1];
    g_grid[b*HW_ + r*W_ + c] = n;
}

// ---------------------------------------------------------------
// K2: LN + fused QKV as a block-tiled GEMM (128 pts x 96 ch x 32 k)
//     point-pair packed f32x2; smem-transposed coalesced stores.
//     NOTE: ln_w/ln_b read directly from global (uniform broadcast) —
//     no smem staging, avoids the pre-sync race that sank R3.
// ---------------------------------------------------------------
__global__ void __launch_bounds__(256) k_qkv(const float* __restrict__ feats,
                                             const float* __restrict__ ln_w,
                                             const float* __restrict__ ln_b){
    __shared__ __align__(16) u64  shA2[32*96];          // [e][ch] duplicated pairs, 24KB
    __shared__ __align__(16) char shU[128*37*4];        // union: Xs f32[32][128] / Ys f32[128][37]
    __shared__ float shB[96];
    float* Xs = (float*)shU;
    float* Ys = (float*)shU;
    int t = threadIdx.x;
    int p0 = blockIdx.x*128;
    if (t >= 128){
        int u = t - 128;
#pragma unroll
        for (int it = 0; it < 24; it++){
            int i = u + 128*it;
            float v = g_A[i];
            int ch = i >> 5, e = i & 31;
            shA2[e*96 + ch] = pk2(v, v);
        }
        if (u < 96) shB[u] = g_bf[u];
    } else {
        int p = p0 + t;   // grid sized exactly: 1875*128 == 240000
        const float4* xin = (const float4*)(feats + (size_t)p*C_);
        float x[32];
#pragma unroll
        for (int k = 0; k < 8; k++){
            float4 v = xin[k];
            x[4*k] = v.x; x[4*k+1] = v.y; x[4*k+2] = v.z; x[4*k+3] = v.w;
        }
        float mu = 0.f;
#pragma unroll
        for (int e = 0; e < 32; e++) mu += x[e];
        mu *= (1.f/32.f);
        float var = 0.f;
#pragma unroll
        for (int e = 0; e < 32; e++){ float d = x[e]-mu; var += d*d; }
        var *= (1.f/32.f);
        float inv = rsqrtf(var + 1e-5f);
#pragma unroll
        for (int k = 0; k < 32; k++)
            Xs[k*128 + t] = (x[k]-mu)*inv*__ldg(&ln_w[k]) + __ldg(&ln_b[k]);
    }
    __syncthreads();

    // GEMM: thread (i,j): points 8i..8i+7 (4 u64 pairs), channels {j+16cc}
    int i = t >> 4, j = t & 15;
    u64 acc[6][4];
#pragma unroll
    for (int cc = 0; cc < 6; cc++){
        float b = shB[j + 16*cc];
        u64 bb = pk2(b, b);
#pragma unroll
        for (int mm = 0; mm < 4; mm++) acc[cc][mm] = bb;
    }
#pragma unroll 4
    for (int e = 0; e < 32; e++){
        const u64* xr = (const u64*)(Xs + e*128) + i*4;
        ulonglong2 xa = *(const ulonglong2*)(xr);
        ulonglong2 xb = *(const ulonglong2*)(xr + 2);
        u64 xv[4] = {xa.x, xa.y, xb.x, xb.y};
        const u64* ar = shA2 + e*96 + j;
        u64 av[6];
#pragma unroll
        for (int cc = 0; cc < 6; cc++) av[cc] = ar[16*cc];
#pragma unroll
        for (int cc = 0; cc < 6; cc++)
#pragma unroll
            for (int mm = 0; mm < 4; mm++)
                acc[cc][mm] = ffma2(av[cc], xv[mm], acc[cc][mm]);
    }

    // store via smem transpose, one matrix at a time (coalesced float4 out)
#pragma unroll
    for (int m = 0; m < 3; m++){
        __syncthreads();
#pragma unroll
        for (int cc2 = 0; cc2 < 2; cc2++){
            int cc = 2*m + cc2;
            int cl = j + 16*cc2;
#pragma unroll
            for (int mm = 0; mm < 4; mm++){
                float2 f = unpk2(acc[cc][mm]);
                Ys[(8*i + 2*mm    )*37 + cl] = f.x;
                Ys[(8*i + 2*mm + 1)*37 + cl] = f.y;
            }
        }
        __syncthreads();
        float* dst = (m==0) ? g_Q : (m==1) ? g_K : g_V;
        int p = t >> 1, h = t & 1;
        const float* yr = Ys + p*37 + 16*h;
        float4* gd = (float4*)(dst + (size_t)(p0 + p)*C_ + 16*h);
#pragma unroll
        for (int q = 0; q < 4; q++)
            gd[q] = make_float4(yr[4*q], yr[4*q+1], yr[4*q+2], yr[4*q+3]);
    }
}

// ---------------------------------------------------------------
// K3: per-point 9-neighbor 2-head attention; output projection as
//     block-tiled GEMM through shared (256 pts x 32 ch x 32 k)
// ---------------------------------------------------------------
__global__ void __launch_bounds__(256) k_attn(const int* __restrict__ coors,
                                              const float* __restrict__ in_b,
                                              const float* __restrict__ out_w,
                                              const float* __restrict__ out_b){
    __shared__ __align__(16) u64   shWt2[32*32];        // [k][c] dup pairs of out_w[c][k], 8KB
    __shared__ __align__(16) float shOs[32*260];        // [k][p] staged ov, 33.3KB
    __shared__ __align__(16) float shPos[9*32];
    __shared__ __align__(16) float shKinv[32];
    __shared__ __align__(16) float shVinv[32];
    __shared__ float shOB[32];
    int t = threadIdx.x;
#pragma unroll
    for (int it = 0; it < 4; it++){
        int idx2 = t + 256*it;          // 1024 elems
        int k = idx2 >> 5, c = idx2 & 31;
        float w = out_w[c*32 + k];
        shWt2[idx2] = pk2(w, w);
    }
    for (int idx2 = t; idx2 < 288; idx2 += 256) shPos[idx2] = g_posP[idx2];
    if (t < 32){ shKinv[t] = in_b[32+t]; shVinv[t] = in_b[64+t]; shOB[t] = out_b[t]; }
    __syncthreads();

    int pbase = blockIdx.x*256;
    int p  = pbase + t;
    int pc = (p < NP_) ? p : (NP_ - 1);
    int b  = pc / N_;

    const float4* qin = (const float4*)(g_Q + (size_t)pc*C_);
    u64 qp[16];
#pragma unroll
    for (int k = 0; k < 8; k++){
        float4 v = qin[k];
        qp[2*k] = pk2(v.x, v.y); qp[2*k+1] = pk2(v.z, v.w);
    }
    int r0 = coors[2*pc], c0 = coors[2*pc+1];
    const int* grid = g_grid + b*HW_;
    const int dr[9] = {0,-1,1,0,-1,1,0,-1,1};
    const int dc[9] = {0,0,0,1,1,1,-1,-1,-1};
    int idx[9];
#pragma unroll
    for (int s = 0; s < 9; s++){
        int rr = r0 + dr[s], cc = c0 + dc[s];
        bool ok = (rr >= 0) && (rr < H_) && (cc >= 0) && (cc < W_);
        idx[s] = ok ? grid[rr*W_ + cc] : -1;
    }
    // invalid-slot logit: q . in_b[C:2C]
    const u64* kinvp = (const u64*)shKinv;
    u64 ai0 = 0ull, ai1 = 0ull;
#pragma unroll
    for (int k = 0; k < 8; k++){
        ai0 = ffma2(qp[k],   kinvp[k],   ai0);
        ai1 = ffma2(qp[8+k], kinvp[8+k], ai1);
    }
    float linv0 = hsum2(ai0), linv1 = hsum2(ai1);

    float lg[18];
#pragma unroll
    for (int s = 0; s < 9; s++){
        if (idx[s] >= 0){
            const float4* kr = (const float4*)(g_K + (size_t)(b*N_ + idx[s])*C_);
            u64 a0 = 0ull, a1 = 0ull;
#pragma unroll
            for (int k = 0; k < 4; k++){
                float4 v = kr[k];
                a0 = ffma2(qp[2*k],   pk2(v.x, v.y), a0);
                a0 = ffma2(qp[2*k+1], pk2(v.z, v.w), a0);
            }
#pragma unroll
            for (int k = 4; k < 8; k++){
                float4 v = kr[k];
                a1 = ffma2(qp[2*k],   pk2(v.x, v.y), a1);
                a1 = ffma2(qp[2*k+1], pk2(v.z, v.w), a1);
            }
            lg[s] = hsum2(a0); lg[9+s] = hsum2(a1);
        } else {
            lg[s] = linv0; lg[9+s] = linv1;
        }
    }
    float m0 = lg[0], m1 = lg[9];
#pragma unroll
    for (int s = 1; s < 9; s++){ m0 = fmaxf(m0, lg[s]); m1 = fmaxf(m1, lg[9+s]); }
    float sum0 = 0.f, sum1 = 0.f;
#pragma unroll
    for (int s = 0; s < 9; s++){
        lg[s]   = __expf(lg[s]   - m0); sum0 += lg[s];
        lg[9+s] = __expf(lg[9+s] - m1); sum1 += lg[9+s];
    }
    float rs0 = 1.f/sum0, rs1 = 1.f/sum1;

    u64 ov[16];
#pragma unroll
    for (int k = 0; k < 16; k++) ov[k] = 0ull;
    float w0inv = 0.f, w1inv = 0.f;
#pragma unroll
    for (int s = 0; s < 9; s++){
        float ws0 = lg[s]*rs0, ws1 = lg[9+s]*rs1;
        if (idx[s] >= 0){
            const float4* vr = (const float4*)(g_V + (size_t)(b*N_ + idx[s])*C_);
            const float4* pr = (const float4*)&shPos[s*32];
            u64 W0 = pk2(ws0, ws0), W1 = pk2(ws1, ws1);
#pragma unroll
            for (int k = 0; k < 4; k++){
                float4 v = vr[k]; float4 pp = pr[k];
                ov[2*k]   = ffma2(W0, pk2(v.x+pp.x, v.y+pp.y), ov[2*k]);
                ov[2*k+1] = ffma2(W0, pk2(v.z+pp.z, v.w+pp.w), ov[2*k+1]);
            }
#pragma unroll
            for (int k = 4; k < 8; k++){
                float4 v = vr[k]; float4 pp = pr[k];
                ov[2*k]   = ffma2(W1, pk2(v.x+pp.x, v.y+pp.y), ov[2*k]);
                ov[2*k+1] = ffma2(W1, pk2(v.z+pp.z, v.w+pp.w), ov[2*k+1]);
            }
        } else { w0inv += ws0; w1inv += ws1; }
    }
    {
        const u64* vinvp = (const u64*)shVinv;
        u64 W0 = pk2(w0inv, w0inv), W1 = pk2(w1inv, w1inv);
#pragma unroll
        for (int k = 0; k < 8; k++){
            ov[k]   = ffma2(W0, vinvp[k],   ov[k]);
            ov[8+k] = ffma2(W1, vinvp[8+k], ov[8+k]);
        }
    }
    // stage ov[32 floats] into shOs[k][p]
#pragma unroll
    for (int k = 0; k < 16; k++){
        float2 f = unpk2(ov[k]);
        shOs[(2*k  )*260 + t] = f.x;
        shOs[(2*k+1)*260 + t] = f.y;
    }
    __syncthreads();

    // output projection GEMM: thread (i,j): points 8i.. (4 pairs), channels {j+8cc}
    int i = t >> 3, j = t & 7;
    u64 acc[4][4];
#pragma unroll
    for (int cc = 0; cc < 4; cc++){
        float bb = shOB[j + 8*cc];
        u64 b2 = pk2(bb, bb);
#pragma unroll
        for (int mm = 0; mm < 4; mm++) acc[cc][mm] = b2;
    }
#pragma unroll 4
    for (int e = 0; e < 32; e++){
        const u64* xr = (const u64*)(shOs + e*260) + i*4;
        ulonglong2 xa = *(const ulonglong2*)(xr);
        ulonglong2 xb = *(const ulonglong2*)(xr + 2);
        u64 xv[4] = {xa.x, xa.y, xb.x, xb.y};
        const u64* wr = shWt2 + e*32 + j;
        u64 av[4];
#pragma unroll
        for (int cc = 0; cc < 4; cc++) av[cc] = wr[8*cc];
#pragma unroll
        for (int cc = 0; cc < 4; cc++)
#pragma unroll
            for (int mm = 0; mm < 4; mm++)
                acc[cc][mm] = ffma2(av[cc], xv[mm], acc[cc][mm]);
    }
#pragma unroll
    for (int cc = 0; cc < 4; cc++)
#pragma unroll
        for (int mm = 0; mm < 4; mm++){
            int pt = pbase + 8*i + 2*mm;
            if (pt < NP_){
                float2 f = unpk2(acc[cc][mm]);
                g_O[(size_t)pt*C_       + j + 8*cc] = f.x;
                g_O[(size_t)(pt+1)*C_   + j + 8*cc] = f.y;
            }
        }
}

// ---------------------------------------------------------------
// K4: expand to [B,C,H,W] — full-row gathers + smem transpose,
//     coalesced channel-major stores
// ---------------------------------------------------------------
__global__ void __launch_bounds__(256) k_expand(float* __restrict__ out){
    __shared__ float sm[256*33];
    int b   = blockIdx.y;
    int hw0 = blockIdx.x * 256;
    int t   = threadIdx.x;
    int hw  = hw0 + t;
    int idx = g_grid[b*HW_ + hw];
    if (idx >= 0){
        const float4* orow = (const float4*)(g_O + (size_t)(b*N_ + idx)*C_);
#pragma unroll
        for (int k = 0; k < 8; k++){
            float4 v = orow[k];
            sm[t*33 + 4*k + 0] = v.x; sm[t*33 + 4*k + 1] = v.y;
            sm[t*33 + 4*k + 2] = v.z; sm[t*33 + 4*k + 3] = v.w;
        }
    } else {
#pragma unroll
        for (int c = 0; c < 32; c++) sm[t*33 + c] = 0.f;
    }
    __syncthreads();
#pragma unroll
    for (int c = 0; c < 32; c++)
        out[((size_t)(b*C_ + c))*HW_ + hw] = sm[t*33 + c];
}

// ---------------------------------------------------------------
extern "C" void kernel_launch(void* const* d_in, const int* in_sizes, int n_in,
                              void* d_out, int out_size){
    const float* feats = (const float*)d_in[0];
    const int*   coors = (const int*)  d_in[1];
    const float* ln_w  = (const float*)d_in[2];
    const float* ln_b  = (const float*)d_in[3];
    const float* wq    = (const float*)d_in[4];
    const float* bq    = (const float*)d_in[5];
    const float* wk    = (const float*)d_in[6];
    const float* bk    = (const float*)d_in[7];
    const float* wv    = (const float*)d_in[8];
    const float* bv    = (const float*)d_in[9];
    const float* pos_w = (const float*)d_in[10];
    const float* pos_b = (const float*)d_in[11];
    const float* in_w  = (const float*)d_in[12];
    const float* in_b  = (const float*)d_in[13];
    const float* out_w = (const float*)d_in[14];
    const float* out_b = (const float*)d_in[15];

    k_setup<<<1, 96>>>(wq, bq, wk, bk, wv, bv, in_w, in_b, pos_w, pos_b);
    k_grid_clear<<<(B_*HW_ + 255)/256, 256>>>();
    k_grid_fill<<<(NP_ + 255)/256, 256>>>(coors);
    k_qkv<<<NP_/128, 256>>>(feats, ln_w, ln_b);
    k_attn<<<(NP_ + 255)/256, 256>>>(coors, in_b, out_w, out_b);
    k_expand<<<dim3(HW_/256, B_), 256>>>((float*)d_out);
}

// round 6
// speedup vs baseline: 1.2141x; 1.2021x over previous
#include <cuda_runtime.h>
#include <cuda_fp16.h>

#define H_ 512
#define W_ 512
#define C_ 32
#define B_ 2
#define N_ 120000
#define HW_ (H_*W_)
#define NP_ (B_*N_)

typedef unsigned long long u64;

// ---- device scratch (no allocations allowed) ----
__device__ __align__(128) float  g_Q[NP_*C_];
__device__ __align__(128) __half g_Kh[NP_*C_];
__device__ __align__(128) float  g_V[NP_*C_];
__device__ __align__(128) float  g_Osp[B_*HW_*C_];   // spatial O (only valid cells written)
__device__ int   g_grid[B_*HW_];
__device__ float g_A[3*1024];     // fused A_q(*0.25), A_k, A_v  ([ch][e], ch=m*32+c)
__device__ float g_bf[3*32];      // fused biases (q scaled by 0.25)
__device__ u64   g_A2p[32*48];    // channel-pair packed: [e][m*16+j] = (A[2j][e],A[2j+1][e])
__device__ u64   g_bf2[48];       // packed bias pairs
__device__ float g_posP[9*32];    // pos embedding projected through in_w[2C:]

// ---- packed f32x2 helpers ----
__device__ __forceinline__ u64 pk2(float lo, float hi){
    u64 r; asm("mov.b64 %0, {%1, %2};" : "=l"(r) : "f"(lo), "f"(hi)); return r;
}
__device__ __forceinline__ float2 unpk2(u64 v){
    float2 f; asm("mov.b64 {%0, %1}, %2;" : "=f"(f.x), "=f"(f.y) : "l"(v)); return f;
}
__device__ __forceinline__ u64 ffma2(u64 a, u64 b, u64 c){
    u64 d; asm("fma.rn.f32x2 %0, %1, %2, %3;" : "=l"(d) : "l"(a), "l"(b), "l"(c)); return d;
}
__device__ __forceinline__ float hsum2(u64 a){ float2 f = unpk2(a); return f.x + f.y; }
__device__ __forceinline__ u64 h2f2(unsigned v){
    __half2 h = *reinterpret_cast<__half2*>(&v);
    float2 f = __half22float2(h);
    return pk2(f.x, f.y);
}

// ---------------------------------------------------------------
// K0: fold (wq,bq,in_w[:C],in_b[:C]) -> A_q,b_q (scaled 0.25), etc. + posP
// ---------------------------------------------------------------
__global__ void k_setup(const float* __restrict__ wq, const float* __restrict__ bq,
                        const float* __restrict__ wk, const float* __restrict__ bk,
                        const float* __restrict__ wv, const float* __restrict__ bv,
                        const float* __restrict__ in_w, const float* __restrict__ in_b,
                        const float* __restrict__ pos_w, const float* __restrict__ pos_b){
    int t = threadIdx.x;
    if (t >= 96) return;
    int m = t >> 5, c = t & 31;
    const float* Wm = (m==0) ? wq : (m==1) ? wk : wv;
    const float* bm = (m==0) ? bq : (m==1) ? bk : bv;
    const float* iw = in_w + (m*32 + c)*32;
    float scale = (m==0) ? 0.25f : 1.0f;   // 1/sqrt(HD=16)
    for (int e = 0; e < 32; e++){
        float a = 0.f;
        for (int d = 0; d < 32; d++) a += iw[d] * Wm[d*32 + e];
        g_A[m*1024 + c*32 + e] = a * scale;
    }
    float bb = 0.f;
    for (int d = 0; d < 32; d++) bb += iw[d] * bm[d];
    g_bf[m*32 + c] = (bb + in_b[m*32 + c]) * scale;
    if (m == 2){
        const int dr[9] = {0,-1,1,0,-1,1,0,-1,1};
        const int dc[9] = {0,0,0,1,1,1,-1,-1,-1};
        for (int s = 0; s < 9; s++){
            float a = 0.f;
            for (int d = 0; d < 32; d++){
                float pos = (float)dr[s]*pos_w[d*2+0] + (float)dc[s]*pos_w[d*2+1] + pos_b[d];
                a += iw[d] * pos;
            }
            g_posP[s*32 + c] = a;
        }
    }
}

// K0b: channel-pair packing of A and biases
__global__ void k_pack(){
    int t = threadIdx.x;
    for (int idx = t; idx < 1536; idx += 256){
        int e = idx & 31, jj = idx >> 5;      // jj = m*16 + j
        int m = jj >> 4, j = jj & 15;
        float v0 = g_A[(m*32 + 2*j    )*32 + e];
        float v1 = g_A[(m*32 + 2*j + 1)*32 + e];
        g_A2p[e*48 + jj] = pk2(v0, v1);
    }
    if (t < 48){
        int m = t >> 4, j = t & 15;
        g_bf2[t] = pk2(g_bf[m*32 + 2*j], g_bf[m*32 + 2*j + 1]);
    }
}

// ---------------------------------------------------------------
// K1: dense grid build
// ---------------------------------------------------------------
__global__ void k_grid_clear(){
    int i = blockIdx.x*blockDim.x + threadIdx.x;
    if (i < B_*HW_) g_grid[i] = -1;
}
__global__ void k_grid_fill(const int* __restrict__ coors){
    int p = blockIdx.x*blockDim.x + threadIdx.x;
    if (p >= NP_) return;
    int b = p / N_, n = p % N_;
    int r = coors[2*p], c = coors[2*p+1];
    g_grid[b*HW_ + r*W_ + c] = n;
}

// ---------------------------------------------------------------
// K2: LN + fused QKV GEMM, channel-pair packed: NO output transpose.
//     thread (i,j): points 8i..8i+7, channel pair (2j,2j+1) of each matrix.
// ---------------------------------------------------------------
__global__ void __launch_bounds__(256) k_qkv(const float* __restrict__ feats,
                                             const float* __restrict__ ln_w,
                                             const float* __restrict__ ln_b){
    __shared__ __align__(16) u64 shA2p[32*48];   // 12KB
    __shared__ __align__(16) u64 Xs2[32*128];    // 32KB, [e][p] = (x,x)
    __shared__ __align__(16) u64 shBp[48];
    int t = threadIdx.x;
    int p0 = blockIdx.x*128;
    if (t >= 128){
        int u = t - 128;
#pragma unroll
        for (int it = 0; it < 12; it++) shA2p[u + 128*it] = g_A2p[u + 128*it];
        if (u < 48) shBp[u] = g_bf2[u];
    } else {
        int p = p0 + t;   // grid sized exactly: 1875*128 == 240000
        const float4* xin = (const float4*)(feats + (size_t)p*C_);
        float x[32];
#pragma unroll
        for (int k = 0; k < 8; k++){
            float4 v = xin[k];
            x[4*k] = v.x; x[4*k+1] = v.y; x[4*k+2] = v.z; x[4*k+3] = v.w;
        }
        float mu = 0.f;
#pragma unroll
        for (int e = 0; e < 32; e++) mu += x[e];
        mu *= (1.f/32.f);
        float var = 0.f;
#pragma unroll
        for (int e = 0; e < 32; e++){ float d = x[e]-mu; var += d*d; }
        var *= (1.f/32.f);
        float inv = rsqrtf(var + 1e-5f);
#pragma unroll
        for (int k = 0; k < 32; k++){
            float v = (x[k]-mu)*inv*__ldg(&ln_w[k]) + __ldg(&ln_b[k]);
            Xs2[k*128 + t] = pk2(v, v);
        }
    }
    __syncthreads();

    int i = t >> 4, j = t & 15;
    u64 acc0[8], acc1[8], acc2[8];
    {
        u64 b0 = shBp[j], b1 = shBp[16 + j], b2 = shBp[32 + j];
#pragma unroll
        for (int p8 = 0; p8 < 8; p8++){ acc0[p8] = b0; acc1[p8] = b1; acc2[p8] = b2; }
    }
#pragma unroll 2
    for (int e = 0; e < 32; e++){
        const ulonglong2* xr = (const ulonglong2*)(Xs2 + e*128 + i*8);
        ulonglong2 x0 = xr[0], x1 = xr[1], x2 = xr[2], x3 = xr[3];
        u64 xd[8] = {x0.x, x0.y, x1.x, x1.y, x2.x, x2.y, x3.x, x3.y};
        u64 a0 = shA2p[e*48 + j];
        u64 a1 = shA2p[e*48 + 16 + j];
        u64 a2 = shA2p[e*48 + 32 + j];
#pragma unroll
        for (int p8 = 0; p8 < 8; p8++){
            acc0[p8] = ffma2(a0, xd[p8], acc0[p8]);
            acc1[p8] = ffma2(a1, xd[p8], acc1[p8]);
            acc2[p8] = ffma2(a2, xd[p8], acc2[p8]);
        }
    }
    int prow = p0 + 8*i;
#pragma unroll
    for (int p8 = 0; p8 < 8; p8++)
        *(u64*)(g_Q + (size_t)(prow+p8)*C_ + 2*j) = acc0[p8];
#pragma unroll
    for (int p8 = 0; p8 < 8; p8++){
        float2 f = unpk2(acc1[p8]);
        *(__half2*)(g_Kh + (size_t)(prow+p8)*C_ + 2*j) = __floats2half2_rn(f.x, f.y);
    }
#pragma unroll
    for (int p8 = 0; p8 < 8; p8++)
        *(u64*)(g_V + (size_t)(prow+p8)*C_ + 2*j) = acc2[p8];
}

// ---------------------------------------------------------------
// K3: per-point 9-neighbor 2-head attention (K fp16 gather);
//     output projection GEMM; stores O in SPATIAL layout.
// ---------------------------------------------------------------
__global__ void __launch_bounds__(256) k_attn(const int* __restrict__ coors,
                                              const float* __restrict__ in_b,
                                              const float* __restrict__ out_w,
                                              const float* __restrict__ out_b){
    __shared__ __align__(16) u64   shWt2[32*32];        // [k][c] dup pairs of out_w[c][k], 8KB
    __shared__ __align__(16) float shOs[32*260];        // [k][p] staged ov, 33.3KB
    __shared__ __align__(16) float shPos[9*32];
    __shared__ __align__(16) float shKinv[32];
    __shared__ __align__(16) float shVinv[32];
    __shared__ float shOB[32];
    __shared__ int   shHW[256];                         // per-point flat cell index
    int t = threadIdx.x;
#pragma unroll
    for (int it = 0; it < 4; it++){
        int idx2 = t + 256*it;          // 1024 elems
        int k = idx2 >> 5, c = idx2 & 31;
        float w = out_w[c*32 + k];
        shWt2[idx2] = pk2(w, w);
    }
    for (int idx2 = t; idx2 < 288; idx2 += 256) shPos[idx2] = g_posP[idx2];
    if (t < 32){ shKinv[t] = in_b[32+t]; shVinv[t] = in_b[64+t]; shOB[t] = out_b[t]; }
    __syncthreads();

    int pbase = blockIdx.x*256;
    int p  = pbase + t;
    int pc = (p < NP_) ? p : (NP_ - 1);
    int b  = pc / N_;

    const float4* qin = (const float4*)(g_Q + (size_t)pc*C_);
    u64 qp[16];
#pragma unroll
    for (int k = 0; k < 8; k++){
        float4 v = qin[k];
        qp[2*k] = pk2(v.x, v.y); qp[2*k+1] = pk2(v.z, v.w);
    }
    int r0 = coors[2*pc], c0 = coors[2*pc+1];
    shHW[t] = b*HW_ + r0*W_ + c0;
    const int* grid = g_grid + b*HW_;
    const int dr[9] = {0,-1,1,0,-1,1,0,-1,1};
    const int dc[9] = {0,0,0,1,1,1,-1,-1,-1};
    int idx[9];
#pragma unroll
    for (int s = 0; s < 9; s++){
        int rr = r0 + dr[s], cc = c0 + dc[s];
        bool ok = (rr >= 0) && (rr < H_) && (cc >= 0) && (cc < W_);
        idx[s] = ok ? grid[rr*W_ + cc] : -1;
    }
    // invalid-slot logit: q . in_b[C:2C]
    const u64* kinvp = (const u64*)shKinv;
    u64 ai0 = 0ull, ai1 = 0ull;
#pragma unroll
    for (int k = 0; k < 8; k++){
        ai0 = ffma2(qp[k],   kinvp[k],   ai0);
        ai1 = ffma2(qp[8+k], kinvp[8+k], ai1);
    }
    float linv0 = hsum2(ai0), linv1 = hsum2(ai1);

    float lg[18];
#pragma unroll
    for (int s = 0; s < 9; s++){
        if (idx[s] >= 0){
            const uint4* kr = (const uint4*)(g_Kh + (size_t)(b*N_ + idx[s])*C_);
            uint4 kw0 = kr[0], kw1 = kr[1], kw2 = kr[2], kw3 = kr[3];
            unsigned ww[16] = {kw0.x,kw0.y,kw0.z,kw0.w, kw1.x,kw1.y,kw1.z,kw1.w,
                               kw2.x,kw2.y,kw2.z,kw2.w, kw3.x,kw3.y,kw3.z,kw3.w};
            u64 a0 = 0ull, a1 = 0ull;
#pragma unroll
            for (int k = 0; k < 8; k++)  a0 = ffma2(qp[k],   h2f2(ww[k]),   a0);
#pragma unroll
            for (int k = 0; k < 8; k++)  a1 = ffma2(qp[8+k], h2f2(ww[8+k]), a1);
            lg[s] = hsum2(a0); lg[9+s] = hsum2(a1);
        } else {
            lg[s] = linv0; lg[9+s] = linv1;
        }
    }
    float m0 = lg[0], m1 = lg[9];
#pragma unroll
    for (int s = 1; s < 9; s++){ m0 = fmaxf(m0, lg[s]); m1 = fmaxf(m1, lg[9+s]); }
    float sum0 = 0.f, sum1 = 0.f;
#pragma unroll
    for (int s = 0; s < 9; s++){
        lg[s]   = __expf(lg[s]   - m0); sum0 += lg[s];
        lg[9+s] = __expf(lg[9+s] - m1); sum1 += lg[9+s];
    }
    float rs0 = 1.f/sum0, rs1 = 1.f/sum1;

    u64 ov[16];
#pragma unroll
    for (int k = 0; k < 16; k++) ov[k] = 0ull;
    float w0inv = 0.f, w1inv = 0.f;
#pragma unroll
    for (int s = 0; s < 9; s++){
        float ws0 = lg[s]*rs0, ws1 = lg[9+s]*rs1;
        if (idx[s] >= 0){
            const float4* vr = (const float4*)(g_V + (size_t)(b*N_ + idx[s])*C_);
            const float4* pr = (const float4*)&shPos[s*32];
            u64 W0 = pk2(ws0, ws0), W1 = pk2(ws1, ws1);
#pragma unroll
            for (int k = 0; k < 4; k++){
                float4 v = vr[k]; float4 pp = pr[k];
                ov[2*k]   = ffma2(W0, pk2(v.x+pp.x, v.y+pp.y), ov[2*k]);
                ov[2*k+1] = ffma2(W0, pk2(v.z+pp.z, v.w+pp.w), ov[2*k+1]);
            }
#pragma unroll
            for (int k = 4; k < 8; k++){
                float4 v = vr[k]; float4 pp = pr[k];
                ov[2*k]   = ffma2(W1, pk2(v.x+pp.x, v.y+pp.y), ov[2*k]);
                ov[2*k+1] = ffma2(W1, pk2(v.z+pp.z, v.w+pp.w), ov[2*k+1]);
            }
        } else { w0inv += ws0; w1inv += ws1; }
    }
    {
        const u64* vinvp = (const u64*)shVinv;
        u64 W0 = pk2(w0inv, w0inv), W1 = pk2(w1inv, w1inv);
#pragma unroll
        for (int k = 0; k < 8; k++){
            ov[k]   = ffma2(W0, vinvp[k],   ov[k]);
            ov[8+k] = ffma2(W1, vinvp[8+k], ov[8+k]);
        }
    }
    // stage ov[32 floats] into shOs[k][p]
#pragma unroll
    for (int k = 0; k < 16; k++){
        float2 f = unpk2(ov[k]);
        shOs[(2*k  )*260 + t] = f.x;
        shOs[(2*k+1)*260 + t] = f.y;
    }
    __syncthreads();

    // output projection GEMM: thread (i,j): points 8i.. (4 pairs), channels {j+8cc}
    int i = t >> 3, j = t & 7;
    u64 acc[4][4];
#pragma unroll
    for (int cc = 0; cc < 4; cc++){
        float bb = shOB[j + 8*cc];
        u64 b2 = pk2(bb, bb);
#pragma unroll
        for (int mm = 0; mm < 4; mm++) acc[cc][mm] = b2;
    }
#pragma unroll 4
    for (int e = 0; e < 32; e++){
        const u64* xr = (const u64*)(shOs + e*260) + i*4;
        ulonglong2 xa = *(const ulonglong2*)(xr);
        ulonglong2 xb = *(const ulonglong2*)(xr + 2);
        u64 xv[4] = {xa.x, xa.y, xb.x, xb.y};
        const u64* wr = shWt2 + e*32 + j;
        u64 av[4];
#pragma unroll
        for (int cc = 0; cc < 4; cc++) av[cc] = wr[8*cc];
#pragma unroll
        for (int cc = 0; cc < 4; cc++)
#pragma unroll
            for (int mm = 0; mm < 4; mm++)
                acc[cc][mm] = ffma2(av[cc], xv[mm], acc[cc][mm]);
    }
#pragma unroll
    for (int cc = 0; cc < 4; cc++)
#pragma unroll
        for (int mm = 0; mm < 4; mm++){
            int lidx = 8*i + 2*mm;
            int pt = pbase + lidx;
            if (pt < NP_){   // pt even, NP_ even -> pt+1 < NP_ too
                float2 f = unpk2(acc[cc][mm]);
                g_Osp[(size_t)shHW[lidx  ]*C_ + j + 8*cc] = f.x;
                g_Osp[(size_t)shHW[lidx+1]*C_ + j + 8*cc] = f.y;
            }
        }
}

// ---------------------------------------------------------------
// K4: expand to [B,C,H,W] — ordered sparse row reads + smem transpose,
//     coalesced channel-major stores
// ---------------------------------------------------------------
__global__ void __launch_bounds__(256) k_expand(float* __restrict__ out){
    __shared__ float sm[256*33];
    int b   = blockIdx.y;
    int hw0 = blockIdx.x * 256;
    int t   = threadIdx.x;
    int hw  = hw0 + t;
    int idx = g_grid[b*HW_ + hw];
    if (idx >= 0){
        const float4* orow = (const float4*)(g_Osp + ((size_t)b*HW_ + hw)*C_);
#pragma unroll
        for (int k = 0; k < 8; k++){
            float4 v = orow[k];
            sm[t*33 + 4*k + 0] = v.x; sm[t*33 + 4*k + 1] = v.y;
            sm[t*33 + 4*k + 2] = v.z; sm[t*33 + 4*k + 3] = v.w;
        }
    } else {
#pragma unroll
        for (int c = 0; c < 32; c++) sm[t*33 + c] = 0.f;
    }
    __syncthreads();
#pragma unroll
    for (int c = 0; c < 32; c++)
        out[((size_t)(b*C_ + c))*HW_ + hw] = sm[t*33 + c];
}

// ---------------------------------------------------------------
extern "C" void kernel_launch(void* const* d_in, const int* in_sizes, int n_in,
                              void* d_out, int out_size){
    const float* feats = (const float*)d_in[0];
    const int*   coors = (const int*)  d_in[1];
    const float* ln_w  = (const float*)d_in[2];
    const float* ln_b  = (const float*)d_in[3];
    const float* wq    = (const float*)d_in[4];
    const float* bq    = (const float*)d_in[5];
    const float* wk    = (const float*)d_in[6];
    const float* bk    = (const float*)d_in[7];
    const float* wv    = (const float*)d_in[8];
    const float* bv    = (const float*)d_in[9];
    const float* pos_w = (const float*)d_in[10];
    const float* pos_b = (const float*)d_in[11];
    const float* in_w  = (const float*)d_in[12];
    const float* in_b  = (const float*)d_in[13];
    const float* out_w = (const float*)d_in[14];
    const float* out_b = (const float*)d_in[15];

    k_setup<<<1, 96>>>(wq, bq, wk, bk, wv, bv, in_w, in_b, pos_w, pos_b);
    k_pack<<<1, 256>>>();
    k_grid_clear<<<(B_*HW_ + 255)/256, 256>>>();
    k_grid_fill<<<(NP_ + 255)/256, 256>>>(coors);
    k_qkv<<<NP_/128, 256>>>(feats, ln_w, ln_b);
    k_attn<<<(NP_ + 255)/256, 256>>>(coors, in_b, out_w, out_b);
    k_expand<<<dim3(HW_/256, B_), 256>>>((float*)d_out);
}

// round 7
// speedup vs baseline: 1.3444x; 1.1074x over previous
#include <cuda_runtime.h>
#include <cuda_fp16.h>

#define H_ 512
#define W_ 512
#define C_ 32
#define B_ 2
#define N_ 120000
#define HW_ (H_*W_)
#define NP_ (B_*N_)

typedef unsigned long long u64;

// ---- device scratch (no allocations allowed) ----
__device__ __align__(128) float  g_Q[NP_*C_];
__device__ __align__(128) __half g_KV[NP_*64];       // per-point 128B row: K[32] fp16, V[32] fp16
__device__ __align__(128) float  g_Osp[B_*HW_*C_];   // spatial O (only valid cells written)
__device__ int   g_grid[B_*HW_];
__device__ float g_A[3*1024];     // fused A_q(*0.25), A_k, A_v  ([ch][e], ch=m*32+c)
__device__ float g_bf[3*32];      // fused biases (q scaled by 0.25)
__device__ u64   g_A2p[32*48];    // channel-pair packed: [e][m*16+j] = (A[2j][e],A[2j+1][e])
__device__ u64   g_bf2[48];       // packed bias pairs
__device__ float g_posP[9*32];    // pos embedding projected through in_w[2C:]
__device__ u64   g_posP2[9*16];   // pair-packed posP

// ---- packed f32x2 helpers ----
__device__ __forceinline__ u64 pk2(float lo, float hi){
    u64 r; asm("mov.b64 %0, {%1, %2};" : "=l"(r) : "f"(lo), "f"(hi)); return r;
}
__device__ __forceinline__ float2 unpk2(u64 v){
    float2 f; asm("mov.b64 {%0, %1}, %2;" : "=f"(f.x), "=f"(f.y) : "l"(v)); return f;
}
__device__ __forceinline__ u64 ffma2(u64 a, u64 b, u64 c){
    u64 d; asm("fma.rn.f32x2 %0, %1, %2, %3;" : "=l"(d) : "l"(a), "l"(b), "l"(c)); return d;
}
__device__ __forceinline__ u64 add2(u64 a, u64 b){
    u64 d; asm("add.rn.f32x2 %0, %1, %2;" : "=l"(d) : "l"(a), "l"(b)); return d;
}
__device__ __forceinline__ u64 mul2(u64 a, u64 b){
    u64 d; asm("mul.rn.f32x2 %0, %1, %2;" : "=l"(d) : "l"(a), "l"(b)); return d;
}
__device__ __forceinline__ float hsum2(u64 a){ float2 f = unpk2(a); return f.x + f.y; }
__device__ __forceinline__ u64 h2f2(unsigned v){
    __half2 h = *reinterpret_cast<__half2*>(&v);
    float2 f = __half22float2(h);
    return pk2(f.x, f.y);
}

// ---------------------------------------------------------------
// K0: fold weights + pack (single block, phased with __syncthreads)
// ---------------------------------------------------------------
__global__ void k_setup(const float* __restrict__ wq, const float* __restrict__ bq,
                        const float* __restrict__ wk, const float* __restrict__ bk,
                        const float* __restrict__ wv, const float* __restrict__ bv,
                        const float* __restrict__ in_w, const float* __restrict__ in_b,
                        const float* __restrict__ pos_w, const float* __restrict__ pos_b){
    int t = threadIdx.x;
    if (t < 96){
        int m = t >> 5, c = t & 31;
        const float* Wm = (m==0) ? wq : (m==1) ? wk : wv;
        const float* bm = (m==0) ? bq : (m==1) ? bk : bv;
        const float* iw = in_w + (m*32 + c)*32;
        float scale = (m==0) ? 0.25f : 1.0f;   // 1/sqrt(HD=16)
        for (int e = 0; e < 32; e++){
            float a = 0.f;
            for (int d = 0; d < 32; d++) a += iw[d] * Wm[d*32 + e];
            g_A[m*1024 + c*32 + e] = a * scale;
        }
        float bb = 0.f;
        for (int d = 0; d < 32; d++) bb += iw[d] * bm[d];
        g_bf[m*32 + c] = (bb + in_b[m*32 + c]) * scale;
        if (m == 2){
            const int dr[9] = {0,-1,1,0,-1,1,0,-1,1};
            const int dc[9] = {0,0,0,1,1,1,-1,-1,-1};
            for (int s = 0; s < 9; s++){
                float a = 0.f;
                for (int d = 0; d < 32; d++){
                    float pos = (float)dr[s]*pos_w[d*2+0] + (float)dc[s]*pos_w[d*2+1] + pos_b[d];
                    a += iw[d] * pos;
                }
                g_posP[s*32 + c] = a;
            }
        }
    }
    __syncthreads();
    // phase 2: pair packing
    for (int idx = t; idx < 1536; idx += 256){
        int e = idx & 31, jj = idx >> 5;      // jj = m*16 + j
        int m = jj >> 4, j = jj & 15;
        float v0 = g_A[(m*32 + 2*j    )*32 + e];
        float v1 = g_A[(m*32 + 2*j + 1)*32 + e];
        g_A2p[e*48 + jj] = pk2(v0, v1);
    }
    if (t < 48){
        int m = t >> 4, j = t & 15;
        g_bf2[t] = pk2(g_bf[m*32 + 2*j], g_bf[m*32 + 2*j + 1]);
    }
    if (t >= 64 && t < 208){
        int u = t - 64;                       // 144 pos pairs
        int s = u >> 4, k = u & 15;
        g_posP2[u] = pk2(g_posP[s*32 + 2*k], g_posP[s*32 + 2*k + 1]);
    }
}

// ---------------------------------------------------------------
// K1: dense grid build
// ---------------------------------------------------------------
__global__ void k_grid_clear(){
    int i = blockIdx.x*blockDim.x + threadIdx.x;
    if (i < B_*HW_) g_grid[i] = -1;
}
__global__ void k_grid_fill(const int* __restrict__ coors){
    int p = blockIdx.x*blockDim.x + threadIdx.x;
    if (p >= NP_) return;
    int b = p / N_, n = p % N_;
    int r = coors[2*p], c = coors[2*p+1];
    g_grid[b*HW_ + r*W_ + c] = n;
}

// ---------------------------------------------------------------
// K2: LN + fused QKV GEMM, channel-pair packed, no transpose.
//     Q fp32; K+V interleaved fp16 in one 128B row.
// ---------------------------------------------------------------
__global__ void __launch_bounds__(256) k_qkv(const float* __restrict__ feats,
                                             const float* __restrict__ ln_w,
                                             const float* __restrict__ ln_b){
    __shared__ __align__(16) u64 shA2p[32*48];   // 12KB
    __shared__ __align__(16) u64 Xs2[32*128];    // 32KB, [e][p] = (x,x)
    __shared__ __align__(16) u64 shBp[48];
    int t = threadIdx.x;
    int p0 = blockIdx.x*128;
    if (t >= 128){
        int u = t - 128;
#pragma unroll
        for (int it = 0; it < 12; it++) shA2p[u + 128*it] = g_A2p[u + 128*it];
        if (u < 48) shBp[u] = g_bf2[u];
    } else {
        int p = p0 + t;   // grid sized exactly: 1875*128 == 240000
        const float4* xin = (const float4*)(feats + (size_t)p*C_);
        float x[32];
#pragma unroll
        for (int k = 0; k < 8; k++){
            float4 v = xin[k];
            x[4*k] = v.x; x[4*k+1] = v.y; x[4*k+2] = v.z; x[4*k+3] = v.w;
        }
        float mu = 0.f;
#pragma unroll
        for (int e = 0; e < 32; e++) mu += x[e];
        mu *= (1.f/32.f);
        float var = 0.f;
#pragma unroll
        for (int e = 0; e < 32; e++){ float d = x[e]-mu; var += d*d; }
        var *= (1.f/32.f);
        float inv = rsqrtf(var + 1e-5f);
#pragma unroll
        for (int k = 0; k < 32; k++){
            float v = (x[k]-mu)*inv*__ldg(&ln_w[k]) + __ldg(&ln_b[k]);
            Xs2[k*128 + t] = pk2(v, v);
        }
    }
    __syncthreads();

    int i = t >> 4, j = t & 15;
    u64 acc0[8], acc1[8], acc2[8];
    {
        u64 b0 = shBp[j], b1 = shBp[16 + j], b2 = shBp[32 + j];
#pragma unroll
        for (int p8 = 0; p8 < 8; p8++){ acc0[p8] = b0; acc1[p8] = b1; acc2[p8] = b2; }
    }
#pragma unroll 2
    for (int e = 0; e < 32; e++){
        const ulonglong2* xr = (const ulonglong2*)(Xs2 + e*128 + i*8);
        ulonglong2 x0 = xr[0], x1 = xr[1], x2 = xr[2], x3 = xr[3];
        u64 xd[8] = {x0.x, x0.y, x1.x, x1.y, x2.x, x2.y, x3.x, x3.y};
        u64 a0 = shA2p[e*48 + j];
        u64 a1 = shA2p[e*48 + 16 + j];
        u64 a2 = shA2p[e*48 + 32 + j];
#pragma unroll
        for (int p8 = 0; p8 < 8; p8++){
            acc0[p8] = ffma2(a0, xd[p8], acc0[p8]);
            acc1[p8] = ffma2(a1, xd[p8], acc1[p8]);
            acc2[p8] = ffma2(a2, xd[p8], acc2[p8]);
        }
    }
    int prow = p0 + 8*i;
#pragma unroll
    for (int p8 = 0; p8 < 8; p8++)
        *(u64*)(g_Q + (size_t)(prow+p8)*C_ + 2*j) = acc0[p8];
#pragma unroll
    for (int p8 = 0; p8 < 8; p8++){
        float2 fk = unpk2(acc1[p8]);
        float2 fv = unpk2(acc2[p8]);
        __half* row = g_KV + (size_t)(prow+p8)*64;
        *(__half2*)(row + 2*j)      = __floats2half2_rn(fk.x, fk.y);
        *(__half2*)(row + 32 + 2*j) = __floats2half2_rn(fv.x, fv.y);
    }
}

// ---------------------------------------------------------------
// K3: per-point 9-neighbor 2-head attention — SINGLE PASS:
//     max-free softmax (|logit| small by construction), one 128B KV
//     gather per valid neighbor, online weighted V accumulate.
//     Output projection GEMM; stores O in SPATIAL layout.
// ---------------------------------------------------------------
__global__ void __launch_bounds__(256) k_attn(const int* __restrict__ coors,
                                              const float* __restrict__ in_b,
                                              const float* __restrict__ out_w,
                                              const float* __restrict__ out_b){
    __shared__ __align__(16) u64   shWt2[32*32];        // [k][c] dup pairs of out_w[c][k], 8KB
    __shared__ __align__(16) float shOs[32*260];        // [k][p] staged ov, 33.3KB
    __shared__ __align__(16) u64   shPos2[9*16];        // pair-packed posP
    __shared__ __align__(16) float shKinv[32];
    __shared__ __align__(16) float shVinv[32];
    __shared__ float shOB[32];
    __shared__ int   shHW[256];                         // per-point flat cell index
    int t = threadIdx.x;
#pragma unroll
    for (int it = 0; it < 4; it++){
        int idx2 = t + 256*it;          // 1024 elems
        int k = idx2 >> 5, c = idx2 & 31;
        float w = out_w[c*32 + k];
        shWt2[idx2] = pk2(w, w);
    }
    if (t < 144) shPos2[t] = g_posP2[t];
    if (t >= 160 && t < 192){ int u = t-160; shKinv[u] = in_b[32+u]; }
    if (t >= 192 && t < 224){ int u = t-192; shVinv[u] = in_b[64+u]; }
    if (t >= 224){ int u = t-224; shOB[u] = out_b[u]; }
    __syncthreads();

    int pbase = blockIdx.x*256;
    int p  = pbase + t;
    int pc = (p < NP_) ? p : (NP_ - 1);
    int b  = pc / N_;

    const float4* qin = (const float4*)(g_Q + (size_t)pc*C_);
    u64 qp[16];
#pragma unroll
    for (int k = 0; k < 8; k++){
        float4 v = qin[k];
        qp[2*k] = pk2(v.x, v.y); qp[2*k+1] = pk2(v.z, v.w);
    }
    int r0 = coors[2*pc], c0 = coors[2*pc+1];
    shHW[t] = b*HW_ + r0*W_ + c0;
    const int* grid = g_grid + b*HW_;
    const int dr[9] = {0,-1,1,0,-1,1,0,-1,1};
    const int dc[9] = {0,0,0,1,1,1,-1,-1,-1};
    int idx[9];
#pragma unroll
    for (int s = 0; s < 9; s++){
        int rr = r0 + dr[s], cc = c0 + dc[s];
        bool ok = (rr >= 0) && (rr < H_) && (cc >= 0) && (cc < W_);
        idx[s] = ok ? grid[rr*W_ + cc] : -1;
    }
    // invalid-slot logit: q . in_b[C:2C]
    const u64* kinvp = (const u64*)shKinv;
    u64 ai0 = 0ull, ai1 = 0ull;
#pragma unroll
    for (int k = 0; k < 8; k++){
        ai0 = ffma2(qp[k],   kinvp[k],   ai0);
        ai1 = ffma2(qp[8+k], kinvp[8+k], ai1);
    }
    float linv0 = hsum2(ai0), linv1 = hsum2(ai1);

    // single pass: unnormalized exp weights, online V accumulate
    float sum0 = 0.f, sum1 = 0.f;
    u64 ov[16];
#pragma unroll
    for (int k = 0; k < 16; k++) ov[k] = 0ull;
    int invcnt = 0;
#pragma unroll
    for (int s = 0; s < 9; s++){
        if (idx[s] >= 0){
            const uint4* kv = (const uint4*)(g_KV + (size_t)(b*N_ + idx[s])*64);
            uint4 k0 = kv[0], k1 = kv[1], k2 = kv[2], k3 = kv[3];
            uint4 v0 = kv[4], v1 = kv[5], v2 = kv[6], v3 = kv[7];
            unsigned kw[16] = {k0.x,k0.y,k0.z,k0.w, k1.x,k1.y,k1.z,k1.w,
                               k2.x,k2.y,k2.z,k2.w, k3.x,k3.y,k3.z,k3.w};
            u64 a0 = 0ull, a1 = 0ull;
#pragma unroll
            for (int k = 0; k < 8; k++) a0 = ffma2(qp[k],   h2f2(kw[k]),   a0);
#pragma unroll
            for (int k = 0; k < 8; k++) a1 = ffma2(qp[8+k], h2f2(kw[8+k]), a1);
            float w0 = __expf(hsum2(a0));
            float w1 = __expf(hsum2(a1));
            sum0 += w0; sum1 += w1;
            unsigned vw[16] = {v0.x,v0.y,v0.z,v0.w, v1.x,v1.y,v1.z,v1.w,
                               v2.x,v2.y,v2.z,v2.w, v3.x,v3.y,v3.z,v3.w};
            u64 W0 = pk2(w0, w0), W1 = pk2(w1, w1);
            const u64* pp = shPos2 + s*16;
#pragma unroll
            for (int k = 0; k < 8; k++)
                ov[k]   = ffma2(W0, add2(h2f2(vw[k]),   pp[k]),   ov[k]);
#pragma unroll
            for (int k = 0; k < 8; k++)
                ov[8+k] = ffma2(W1, add2(h2f2(vw[8+k]), pp[8+k]), ov[8+k]);
        } else invcnt++;
    }
    {   // invalid slots: identical logit, closed-form contribution
        float wi0 = __expf(linv0) * (float)invcnt;
        float wi1 = __expf(linv1) * (float)invcnt;
        sum0 += wi0; sum1 += wi1;
        const u64* vinvp = (const u64*)shVinv;
        u64 W0 = pk2(wi0, wi0), W1 = pk2(wi1, wi1);
#pragma unroll
        for (int k = 0; k < 8; k++){
            ov[k]   = ffma2(W0, vinvp[k],   ov[k]);
            ov[8+k] = ffma2(W1, vinvp[8+k], ov[8+k]);
        }
    }
    {   // normalize
        float rs0 = 1.f/sum0, rs1 = 1.f/sum1;
        u64 R0 = pk2(rs0, rs0), R1 = pk2(rs1, rs1);
#pragma unroll
        for (int k = 0; k < 8; k++){
            ov[k]   = mul2(ov[k],   R0);
            ov[8+k] = mul2(ov[8+k], R1);
        }
    }
    // stage ov[32 floats] into shOs[k][p]
#pragma unroll
    for (int k = 0; k < 16; k++){
        float2 f = unpk2(ov[k]);
        shOs[(2*k  )*260 + t] = f.x;
        shOs[(2*k+1)*260 + t] = f.y;
    }
    __syncthreads();

    // output projection GEMM: thread (i,j): points 8i.. (4 pairs), channels {j+8cc}
    int i = t >> 3, j = t & 7;
    u64 acc[4][4];
#pragma unroll
    for (int cc = 0; cc < 4; cc++){
        float bb = shOB[j + 8*cc];
        u64 b2 = pk2(bb, bb);
#pragma unroll
        for (int mm = 0; mm < 4; mm++) acc[cc][mm] = b2;
    }
#pragma unroll 4
    for (int e = 0; e < 32; e++){
        const u64* xr = (const u64*)(shOs + e*260) + i*4;
        ulonglong2 xa = *(const ulonglong2*)(xr);
        ulonglong2 xb = *(const ulonglong2*)(xr + 2);
        u64 xv[4] = {xa.x, xa.y, xb.x, xb.y};
        const u64* wr = shWt2 + e*32 + j;
        u64 av[4];
#pragma unroll
        for (int cc = 0; cc < 4; cc++) av[cc] = wr[8*cc];
#pragma unroll
        for (int cc = 0; cc < 4; cc++)
#pragma unroll
            for (int mm = 0; mm < 4; mm++)
                acc[cc][mm] = ffma2(av[cc], xv[mm], acc[cc][mm]);
    }
#pragma unroll
    for (int cc = 0; cc < 4; cc++)
#pragma unroll
        for (int mm = 0; mm < 4; mm++){
            int lidx = 8*i + 2*mm;
            int pt = pbase + lidx;
            if (pt < NP_){   // pt even, NP_ even -> pt+1 < NP_ too
                float2 f = unpk2(acc[cc][mm]);
                g_Osp[(size_t)shHW[lidx  ]*C_ + j + 8*cc] = f.x;
                g_Osp[(size_t)shHW[lidx+1]*C_ + j + 8*cc] = f.y;
            }
        }
}

// ---------------------------------------------------------------
// K4: expand to [B,C,H,W] — ordered sparse row reads + smem transpose,
//     coalesced channel-major stores
// ---------------------------------------------------------------
__global__ void __launch_bounds__(256) k_expand(float* __restrict__ out){
    __shared__ float sm[256*33];
    int b   = blockIdx.y;
    int hw0 = blockIdx.x * 256;
    int t   = threadIdx.x;
    int hw  = hw0 + t;
    int idx = g_grid[b*HW_ + hw];
    if (idx >= 0){
        const float4* orow = (const float4*)(g_Osp + ((size_t)b*HW_ + hw)*C_);
#pragma unroll
        for (int k = 0; k < 8; k++){
            float4 v = orow[k];
            sm[t*33 + 4*k + 0] = v.x; sm[t*33 + 4*k + 1] = v.y;
            sm[t*33 + 4*k + 2] = v.z; sm[t*33 + 4*k + 3] = v.w;
        }
    } else {
#pragma unroll
        for (int c = 0; c < 32; c++) sm[t*33 + c] = 0.f;
    }
    __syncthreads();
#pragma unroll
    for (int c = 0; c < 32; c++)
        out[((size_t)(b*C_ + c))*HW_ + hw] = sm[t*33 + c];
}

// ---------------------------------------------------------------
extern "C" void kernel_launch(void* const* d_in, const int* in_sizes, int n_in,
                              void* d_out, int out_size){
    const float* feats = (const float*)d_in[0];
    const int*   coors = (const int*)  d_in[1];
    const float* ln_w  = (const float*)d_in[2];
    const float* ln_b  = (const float*)d_in[3];
    const float* wq    = (const float*)d_in[4];
    const float* bq    = (const float*)d_in[5];
    const float* wk    = (const float*)d_in[6];
    const float* bk    = (const float*)d_in[7];
    const float* wv    = (const float*)d_in[8];
    const float* bv    = (const float*)d_in[9];
    const float* pos_w = (const float*)d_in[10];
    const float* pos_b = (const float*)d_in[11];
    const float* in_w  = (const float*)d_in[12];
    const float* in_b  = (const float*)d_in[13];
    const float* out_w = (const float*)d_in[14];
    const float* out_b = (const float*)d_in[15];

    k_setup<<<1, 256>>>(wq, bq, wk, bk, wv, bv, in_w, in_b, pos_w, pos_b);
    k_grid_clear<<<(B_*HW_ + 255)/256, 256>>>();
    k_grid_fill<<<(NP_ + 255)/256, 256>>>(coors);
    k_qkv<<<NP_/128, 256>>>(feats, ln_w, ln_b);
    k_attn<<<(NP_ + 255)/256, 256>>>(coors, in_b, out_w, out_b);
    k_expand<<<dim3(HW_/256, B_), 256>>>((float*)d_out);
}